// round 2
// baseline (speedup 1.0000x reference)
#include <cuda_runtime.h>
#include <math.h>
#include <stdint.h>

// Problem constants
#define Bn    64
#define Hn    1024
#define Tn    500
#define BHn   (Bn*Hn)
#define KC    32
#define NKB   (Hn/KC)     // 32 k-blocks
#define LDA   36          // padded smem row stride (floats)
#define NGEMM 256
#define NPROJ 40
#define NCTA  (NGEMM+NPROJ)  // 296 = 2 per SM on 148 SMs

// ---------------- device scratch (no allocations allowed) ----------------
__device__ float    g_Xt[(size_t)Tn * BHn];   // transposed input (T, B*H) ~131 MB
__device__ float    g_h0[2][BHn];             // layer-0 hidden, double buffered
__device__ float    g_h1[2][BHn];             // layer-1 hidden, double buffered
__device__ unsigned g_cnt;
__device__ unsigned g_gen;

// ---------------- grid barrier (sense via monotonic generation) ----------
__device__ __forceinline__ void grid_bar() {
    __syncthreads();
    __threadfence();
    if (threadIdx.x == 0) {
        unsigned gen  = *(volatile unsigned*)&g_gen;
        unsigned prev = atomicAdd(&g_cnt, 1u);
        if (prev == NCTA - 1u) {
            atomicExch(&g_cnt, 0u);
            __threadfence();
            atomicAdd(&g_gen, 1u);
        } else {
            while (*(volatile unsigned*)&g_gen == gen) __nanosleep(64);
        }
    }
    __syncthreads();
}

// ---------------- transpose: res (B*H, T) -> g_Xt (T, B*H) ---------------
__global__ void k_transpose(const float* __restrict__ src) {
    __shared__ float tile[32][33];
    int t0 = blockIdx.x * 32;
    int r0 = blockIdx.y * 32;
    int tx = threadIdx.x, ty = threadIdx.y;
    #pragma unroll
    for (int i = ty; i < 32; i += 8) {
        int t = t0 + tx;
        tile[i][tx] = (t < Tn) ? src[(size_t)(r0 + i) * Tn + t] : 0.f;
    }
    __syncthreads();
    #pragma unroll
    for (int i = ty; i < 32; i += 8) {
        int t = t0 + i;
        if (t < Tn) g_Xt[(size_t)t * BHn + r0 + tx] = tile[tx][i];
    }
}

// ---------------- cp.async helpers (L1-bypass -> coherent with __stcg) ----
__device__ __forceinline__ void cp16(uint32_t s, const void* g) {
    asm volatile("cp.async.cg.shared.global [%0], [%1], 16;\n" :: "r"(s), "l"(g));
}
__device__ __forceinline__ void cp_commit() {
    asm volatile("cp.async.commit_group;\n");
}
__device__ __forceinline__ void cp_wait0() {
    asm volatile("cp.async.wait_group 0;\n");
}

// ---------------- one GRU layer pass for this CTA's 4 features ------------
// Virtual rows m in [0,24): m = fam*12 + gate*4 + jj
//   fam 0: rows of Wih (dot with Ax), fam 1: rows of Whh (dot with Ah)
// Shared layout (floats): sAx[2][64*36] @0 | sAh[2][64*36] @4608 | sW[2][24*36] @9216
// sC[24*65] aliases @0 (disjoint from all buf-1 regions used by last k-block).
__device__ __noinline__ void gru_phase(
    const float* __restrict__ Ax, const float* __restrict__ Ah,
    float* __restrict__ hnext,
    const float* __restrict__ Wi, const float* __restrict__ Wh,
    const float* __restrict__ bi, const float* __restrict__ bh,
    int j0, float* sm, uint32_t sb)
{
    const int tid = threadIdx.x;
    const int lk  = (tid & 7) * 4;   // k-offset (floats) this thread loads
    const int lr  = tid >> 3;        // base row this thread loads
    const int tb  = tid & 7;         // compute: batch group
    const int tn  = tid >> 3;        // compute: row group (rows tn*3..tn*3+2)

    // global W row pointers for load rows {lr, lr+8, lr+16}
    const float* wp[3];
    #pragma unroll
    for (int i = 0; i < 3; ++i) {
        int m   = lr + 8 * i;
        int fam = (m >= 12);
        int rem = fam ? m - 12 : m;
        int wrow = (rem >> 2) * Hn + j0 + (rem & 3);
        wp[i] = (fam ? Wh : Wi) + (size_t)wrow * Hn;
    }

    // accumulators init with bias (one bias per (row), same across batches)
    float acc[8][3];
    #pragma unroll
    for (int ni = 0; ni < 3; ++ni) {
        int m   = tn * 3 + ni;
        int fam = (m >= 12);
        int rem = fam ? m - 12 : m;
        float bv = (fam ? bh : bi)[(rem >> 2) * Hn + j0 + (rem & 3)];
        #pragma unroll
        for (int q = 0; q < 8; ++q) acc[q][ni] = bv;
    }

    auto load_blk = [&](int kb, int s) {
        uint32_t dAx = sb + (uint32_t)(s * 2304 + lr * LDA + lk) * 4u;
        uint32_t dAh = sb + (uint32_t)(4608 + s * 2304 + lr * LDA + lk) * 4u;
        uint32_t dW  = sb + (uint32_t)(9216 + s * 864  + lr * LDA + lk) * 4u;
        const float* gx = Ax + (size_t)lr * Hn + kb * KC + lk;
        const float* gh = Ah + (size_t)lr * Hn + kb * KC + lk;
        #pragma unroll
        for (int i = 0; i < 8; ++i)
            cp16(dAx + (uint32_t)i * (8 * LDA * 4), gx + (size_t)i * (8 * Hn));
        #pragma unroll
        for (int i = 0; i < 8; ++i)
            cp16(dAh + (uint32_t)i * (8 * LDA * 4), gh + (size_t)i * (8 * Hn));
        #pragma unroll
        for (int i = 0; i < 3; ++i)
            cp16(dW + (uint32_t)i * (8 * LDA * 4), wp[i] + kb * KC + lk);
        cp_commit();
    };

    load_blk(0, 0);
    #pragma unroll 1
    for (int kb = 0; kb < NKB; ++kb) {
        cp_wait0();
        __syncthreads();
        if (kb + 1 < NKB) load_blk(kb + 1, (kb + 1) & 1);
        const int s = kb & 1;
        const float4* pa = (const float4*)(sm + (tn < 4 ? 0 : 4608) + s * 2304);
        const float4* pw = (const float4*)(sm + 9216 + s * 864);
        #pragma unroll
        for (int c = 0; c < 8; ++c) {
            float4 av[8];
            #pragma unroll
            for (int q = 0; q < 8; ++q) av[q] = pa[(tb + 8 * q) * 9 + c];
            float4 wv[3];
            #pragma unroll
            for (int ni = 0; ni < 3; ++ni) wv[ni] = pw[(tn * 3 + ni) * 9 + c];
            #pragma unroll
            for (int q = 0; q < 8; ++q) {
                #pragma unroll
                for (int ni = 0; ni < 3; ++ni) {
                    acc[q][ni] += av[q].x * wv[ni].x;
                    acc[q][ni] += av[q].y * wv[ni].y;
                    acc[q][ni] += av[q].z * wv[ni].z;
                    acc[q][ni] += av[q].w * wv[ni].w;
                }
            }
        }
    }

    // stage partial sums: sC[m][b], stride 65 to spread banks
    float* sC = sm;   // aliases sAx buf0 region; disjoint from buf-1 regions
    #pragma unroll
    for (int ni = 0; ni < 3; ++ni) {
        int m = tn * 3 + ni;
        #pragma unroll
        for (int q = 0; q < 8; ++q) sC[m * 65 + tb + 8 * q] = acc[q][ni];
    }
    __syncthreads();

    // GRU cell combine: thread = batch b, 4 features j0..j0+3
    {
        int b = tid;
        float4 hp = __ldcg((const float4*)(Ah + (size_t)b * Hn + j0));
        float hv[4] = {hp.x, hp.y, hp.z, hp.w};
        float hn4[4];
        #pragma unroll
        for (int jj = 0; jj < 4; ++jj) {
            float ir  = sC[(0  + jj) * 65 + b];
            float iz  = sC[(4  + jj) * 65 + b];
            float inn = sC[(8  + jj) * 65 + b];
            float hr  = sC[(12 + jj) * 65 + b];
            float hz  = sC[(16 + jj) * 65 + b];
            float hnn = sC[(20 + jj) * 65 + b];
            float r = 1.f / (1.f + expf(-(ir + hr)));
            float z = 1.f / (1.f + expf(-(iz + hz)));
            float n = tanhf(inn + r * hnn);
            float hc = (1.f - z) * n + z * hv[jj];
            hn4[jj] = 0.1f * hv[jj] + 0.9f * hc;
        }
        __stcg((float4*)(hnext + (size_t)b * Hn + j0),
               make_float4(hn4[0], hn4[1], hn4[2], hn4[3]));
    }
}

// ---------------- output projection: 4 rows of Wout per CTA ---------------
__device__ __noinline__ void proj_step(
    const float* __restrict__ h1, const float* __restrict__ Wout,
    const float* __restrict__ bout, float* __restrict__ out,
    int r0, int t)
{
    int b = threadIdx.x;   // 64 threads = 64 batches
    float a0 = bout[r0 + 0], a1 = bout[r0 + 1], a2 = bout[r0 + 2], a3 = bout[r0 + 3];
    const float4* pa = (const float4*)(h1 + (size_t)b * Hn);
    const float4* w0 = (const float4*)(Wout + (size_t)(r0 + 0) * Hn);
    const float4* w1 = (const float4*)(Wout + (size_t)(r0 + 1) * Hn);
    const float4* w2 = (const float4*)(Wout + (size_t)(r0 + 2) * Hn);
    const float4* w3 = (const float4*)(Wout + (size_t)(r0 + 3) * Hn);
    #pragma unroll 8
    for (int k = 0; k < Hn / 4; ++k) {
        float4 av = __ldcg(pa + k);
        float4 v0 = __ldg(w0 + k), v1 = __ldg(w1 + k);
        float4 v2 = __ldg(w2 + k), v3 = __ldg(w3 + k);
        a0 += av.x * v0.x + av.y * v0.y + av.z * v0.z + av.w * v0.w;
        a1 += av.x * v1.x + av.y * v1.y + av.z * v1.z + av.w * v1.w;
        a2 += av.x * v2.x + av.y * v2.y + av.z * v2.z + av.w * v2.w;
        a3 += av.x * v3.x + av.y * v3.y + av.z * v3.z + av.w * v3.w;
    }
    // out[b][oc][t*2+rf], oc = r>>1, rf = r&1  (out is (64, 80, 1000))
    size_t ob = (size_t)b * 80000 + (size_t)t * 2;
    out[ob + (size_t)((r0 + 0) >> 1) * 1000 + ((r0 + 0) & 1)] = a0;
    out[ob + (size_t)((r0 + 1) >> 1) * 1000 + ((r0 + 1) & 1)] = a1;
    out[ob + (size_t)((r0 + 2) >> 1) * 1000 + ((r0 + 2) & 1)] = a2;
    out[ob + (size_t)((r0 + 3) >> 1) * 1000 + ((r0 + 3) & 1)] = a3;
}

// ---------------- persistent kernel ---------------------------------------
__global__ void __launch_bounds__(64) k_persistent(
    const float* __restrict__ Wih, const float* __restrict__ Whh,
    const float* __restrict__ bih, const float* __restrict__ bhh,
    const float* __restrict__ Wout, const float* __restrict__ bout,
    float* __restrict__ out)
{
    __shared__ __align__(16) float sm[10944];   // 43776 B
    uint32_t sb = (uint32_t)__cvta_generic_to_shared(sm);
    int cta = blockIdx.x;

    if (cta < NGEMM) {
        int j0 = cta * 4;
        for (int t = 0; t < Tn; ++t) {
            int p = t & 1;
            // layer 0: x_t -> h0
            gru_phase(g_Xt + (size_t)t * BHn, g_h0[p], g_h0[p ^ 1],
                      Wih, Whh, bih, bhh, j0, sm, sb);
            grid_bar();
            // layer 1: h0_new -> h1
            gru_phase(g_h0[p ^ 1], g_h1[p], g_h1[p ^ 1],
                      Wih + 3 * Hn * Hn, Whh + 3 * Hn * Hn,
                      bih + 3 * Hn, bhh + 3 * Hn, j0, sm, sb);
            grid_bar();
        }
    } else {
        int r0 = (cta - NGEMM) * 4;
        for (int t = 0; t < Tn; ++t) {
            // overlap: projection of step t-1 during layer-0 GEMM of step t
            if (t > 0) proj_step(g_h1[t & 1], Wout, bout, out, r0, t - 1);
            grid_bar();
            grid_bar();
        }
        proj_step(g_h1[((Tn - 1) & 1) ^ 1], Wout, bout, out, r0, Tn - 1);
    }
}

// ---------------- launch ---------------------------------------------------
extern "C" void kernel_launch(void* const* d_in, const int* in_sizes, int n_in,
                              void* d_out, int out_size)
{
    const float* res  = (const float*)d_in[0];
    const float* Wih  = (const float*)d_in[1];
    const float* Whh  = (const float*)d_in[2];
    const float* bih  = (const float*)d_in[3];
    const float* bhh  = (const float*)d_in[4];
    const float* Wout = (const float*)d_in[5];
    const float* bout = (const float*)d_in[6];
    float* out = (float*)d_out;
    (void)in_sizes; (void)n_in; (void)out_size;

    // re-zero initial hidden state every call (deterministic across replays)
    void* h0p = nullptr; void* h1p = nullptr;
    cudaGetSymbolAddress(&h0p, g_h0);
    cudaGetSymbolAddress(&h1p, g_h1);
    cudaMemsetAsync(h0p, 0, sizeof(float) * 2 * BHn, 0);
    cudaMemsetAsync(h1p, 0, sizeof(float) * 2 * BHn, 0);

    dim3 tb(32, 8), tg((Tn + 31) / 32, BHn / 32);
    k_transpose<<<tg, tb>>>(res);

    k_persistent<<<NCTA, 64>>>(Wih, Whh, bih, bhh, Wout, bout, out);
}

// round 3
// speedup vs baseline: 1.2301x; 1.2301x over previous
#include <cuda_runtime.h>
#include <math.h>
#include <stdint.h>

// Problem constants
#define Bn    64
#define Hn    1024
#define Tn    500
#define BHn   (Bn*Hn)
#define NGEMM 256
#define NPROJ 40
#define NCTA  (NGEMM+NPROJ)   // 296 = 2 per SM
#define KCQ   16              // k per block per quarter
#define NKBQ  16              // (Hn/4)/KCQ

// Shared-memory layout (float offsets), per CTA:
//   quarter q at q*QSZ:  Ax[2][16*64] | Ah[2][16*64] | W[2][24*20]
//   sC[4][24][66] at SCO
#define QSZ   5056
#define AXO   0
#define AHO   2048
#define WO    4096
#define WBUF  480
#define SCO   20224
#define SCKT  1584
#define SMF   26560
#define SMB   (SMF*4)   // 106240 bytes

// ---------------- device scratch ----------------
__device__ float    g_Xt[(size_t)Tn * BHn];   // (T, H, B): x[t][h][b]
__device__ float    g_h0[2][BHn];             // [j][b] layout, double buffered
__device__ float    g_h1[2][BHn];
__device__ unsigned g_cnt;
__device__ unsigned g_gen;

// ---------------- grid barrier ----------------
__device__ __forceinline__ void grid_bar() {
    __syncthreads();
    __threadfence();
    if (threadIdx.x == 0) {
        unsigned gen  = *(volatile unsigned*)&g_gen;
        unsigned prev = atomicAdd(&g_cnt, 1u);
        if (prev == NCTA - 1u) {
            atomicExch(&g_cnt, 0u);
            __threadfence();
            atomicAdd(&g_gen, 1u);
        } else {
            while (*(volatile unsigned*)&g_gen == gen) __nanosleep(64);
        }
    }
    __syncthreads();
}

// ---------------- transpose: res (B,H,T) -> g_Xt (T,H,B) ------------------
__global__ void k_transpose(const float* __restrict__ src) {
    __shared__ float tile[64][33];
    int h  = blockIdx.y;
    int t0 = blockIdx.x * 32;
    int tx = threadIdx.x, ty = threadIdx.y;   // 32 x 8
    for (int b = ty; b < 64; b += 8) {
        int t = t0 + tx;
        tile[b][tx] = (t < Tn) ? src[((size_t)b * Hn + h) * Tn + t] : 0.f;
    }
    __syncthreads();
    for (int tt = ty; tt < 32; tt += 8) {
        int t = t0 + tt;
        if (t < Tn) {
            g_Xt[(size_t)t * BHn + (size_t)h * 64 + tx]      = tile[tx][tt];
            g_Xt[(size_t)t * BHn + (size_t)h * 64 + 32 + tx] = tile[32 + tx][tt];
        }
    }
}

// ---------------- PTX helpers ----------------
__device__ __forceinline__ void cp16(uint32_t s, const void* g) {
    asm volatile("cp.async.cg.shared.global [%0], [%1], 16;\n" :: "r"(s), "l"(g));
}
__device__ __forceinline__ void cp_commit() { asm volatile("cp.async.commit_group;\n"); }
__device__ __forceinline__ void cp_wait0()  { asm volatile("cp.async.wait_group 0;\n"); }
__device__ __forceinline__ void cp_wait1()  { asm volatile("cp.async.wait_group 1;\n"); }

__device__ __forceinline__ unsigned long long dup2(float w) {
    unsigned long long r;
    asm("mov.b64 %0, {%1, %1};" : "=l"(r) : "r"(__float_as_uint(w)));
    return r;
}
__device__ __forceinline__ void fma2(unsigned long long& d,
                                     unsigned long long a, unsigned long long b) {
    asm("fma.rn.f32x2 %0, %1, %2, %0;" : "+l"(d) : "l"(a), "l"(b));
}

// ---------------- one GRU layer pass (this CTA's 4 features) --------------
// 24 virtual rows m = fam*12 + gate*4 + jj; fam0 dots Ax, fam1 dots Ah.
// A tiles are k-major [k][64 batches]; each warp = one k-quarter (256 k).
// Thread tile: 8 batches x 6 rows as 24 f32x2 accumulators.
__device__ __noinline__ void gru_phase(
    float* sm, uint32_t sb,
    const float* __restrict__ Axg, const float* __restrict__ Ahg,
    float* __restrict__ hnext,
    const float* __restrict__ Wi, const float* __restrict__ Wh,
    const float* __restrict__ bi, const float* __restrict__ bh,
    int j0)
{
    const int tid  = threadIdx.x;
    const int warp = tid >> 5, lane = tid & 31;
    const int tb   = lane & 7, tn = lane >> 3;

    const float* axs = Axg + (size_t)warp * (256 * 64);
    const float* ahs = Ahg + (size_t)warp * (256 * 64);

    // W source pointers for this lane's 3 copy chunks
    const float* wsrc[3];
    #pragma unroll
    for (int i = 0; i < 3; ++i) {
        int c = lane + 32 * i;
        int m = c >> 2;
        int fam = (m >= 12);
        int rem = fam ? m - 12 : m;
        int wrow = (rem >> 2) * Hn + j0 + (rem & 3);
        wsrc[i] = (fam ? Wh : Wi) + (size_t)wrow * Hn + warp * 256 + (c & 3) * 4;
    }
    uint32_t qb   = sb + (uint32_t)warp * (QSZ * 4);
    uint32_t dax0 = qb + AXO * 4 + lane * 16;
    uint32_t dah0 = qb + AHO * 4 + lane * 16;
    uint32_t dw[3];
    #pragma unroll
    for (int i = 0; i < 3; ++i) {
        int c = lane + 32 * i;
        dw[i] = qb + WO * 4 + (uint32_t)(c >> 2) * 80 + (uint32_t)(c & 3) * 16;
    }

    auto load_blk = [&](int kb, int s) {
        uint32_t so = s ? 4096u : 0u;
        const float* ax = axs + kb * 1024;
        const float* ah = ahs + kb * 1024;
        #pragma unroll
        for (int i = 0; i < 8; ++i) cp16(dax0 + so + i * 512, ax + lane * 4 + i * 128);
        #pragma unroll
        for (int i = 0; i < 8; ++i) cp16(dah0 + so + i * 512, ah + lane * 4 + i * 128);
        uint32_t wso = s ? (WBUF * 4u) : 0u;
        #pragma unroll
        for (int i = 0; i < 3; ++i) cp16(dw[i] + wso, wsrc[i] + kb * 16);
        cp_commit();
    };

    unsigned long long acc[6][4];
    #pragma unroll
    for (int ni = 0; ni < 6; ++ni)
        #pragma unroll
        for (int p = 0; p < 4; ++p) acc[ni][p] = 0ull;

    load_blk(0, 0);
    const float* paB = sm + warp * QSZ + (tn < 2 ? AXO : AHO) + tb * 4;
    const float* pwB = sm + warp * QSZ + WO + tn * 120;   // 6*tn rows * 20 stride

    #pragma unroll 1
    for (int kb = 0; kb < NKBQ; ++kb) {
        if (kb + 1 < NKBQ) { load_blk(kb + 1, (kb + 1) & 1); cp_wait1(); }
        else               { cp_wait0(); }
        __syncwarp();
        const float* pa = paB + (kb & 1) * 1024;
        const float* pw = pwB + (kb & 1) * WBUF;
        #pragma unroll
        for (int k = 0; k < KCQ; ++k) {
            const float* rk = pa + k * 64;
            ulonglong2 A0 = *(const ulonglong2*)rk;          // batches 4tb..4tb+3
            ulonglong2 A1 = *(const ulonglong2*)(rk + 32);   // batches 32+4tb..
            #pragma unroll
            for (int ni = 0; ni < 6; ++ni) {
                unsigned long long ww = dup2(pw[ni * 20 + k]);
                fma2(acc[ni][0], A0.x, ww);
                fma2(acc[ni][1], A0.y, ww);
                fma2(acc[ni][2], A1.x, ww);
                fma2(acc[ni][3], A1.y, ww);
            }
        }
    }

    // stage partials: sC[warp][m][batch]
    float* sc = sm + SCO + warp * SCKT;
    #pragma unroll
    for (int ni = 0; ni < 6; ++ni) {
        int m = tn * 6 + ni;
        float* row = sc + m * 66;
        *(unsigned long long*)(row + 4 * tb)          = acc[ni][0];
        *(unsigned long long*)(row + 4 * tb + 2)      = acc[ni][1];
        *(unsigned long long*)(row + 32 + 4 * tb)     = acc[ni][2];
        *(unsigned long long*)(row + 32 + 4 * tb + 2) = acc[ni][3];
    }
    __syncthreads();

    // GRU combine: 128 threads, (batch b, feature pair jp)
    {
        int b = tid & 63, jp = tid >> 6;
        #pragma unroll
        for (int u = 0; u < 2; ++u) {
            int jj = 2 * jp + u;
            float g[6];
            #pragma unroll
            for (int e = 0; e < 6; ++e) {
                int m = e * 4 + jj;
                const float* p = sm + SCO + m * 66 + b;
                g[e] = p[0] + p[SCKT] + p[2 * SCKT] + p[3 * SCKT];
            }
            int j = j0 + jj;
            float ir  = g[0] + bi[j];
            float iz  = g[1] + bi[Hn + j];
            float inn = g[2] + bi[2 * Hn + j];
            float hr  = g[3] + bh[j];
            float hz  = g[4] + bh[Hn + j];
            float hnn = g[5] + bh[2 * Hn + j];
            float hv = __ldcg(Ahg + (size_t)j * 64 + b);
            float r = 1.f / (1.f + expf(-(ir + hr)));
            float z = 1.f / (1.f + expf(-(iz + hz)));
            float n = tanhf(inn + r * hnn);
            float hc = (1.f - z) * n + z * hv;
            __stcg(hnext + (size_t)j * 64 + b, 0.1f * hv + 0.9f * hc);
        }
    }
}

// ---------------- output projection (h1 is [j][b]) ------------------------
__device__ __noinline__ void proj_step(
    const float* __restrict__ h1, const float* __restrict__ Wout,
    const float* __restrict__ bout, float* __restrict__ out,
    int r0, int t)
{
    int b = threadIdx.x & 63, rp = threadIdx.x >> 6;
    int r = r0 + 2 * rp;
    float a0 = bout[r], a1 = bout[r + 1];
    const float* w0 = Wout + (size_t)r * Hn;
    const float* w1 = w0 + Hn;
    #pragma unroll 8
    for (int j = 0; j < Hn; ++j) {
        float hv = __ldcg(h1 + (size_t)j * 64 + b);
        a0 += hv * __ldg(w0 + j);
        a1 += hv * __ldg(w1 + j);
    }
    size_t ob = (size_t)b * 80000 + (size_t)t * 2;
    out[ob + (size_t)(r >> 1) * 1000 + (r & 1)]             = a0;
    out[ob + (size_t)((r + 1) >> 1) * 1000 + ((r + 1) & 1)] = a1;
}

// ---------------- persistent kernel ---------------------------------------
__global__ void __launch_bounds__(128, 2) k_persistent(
    const float* __restrict__ Wih, const float* __restrict__ Whh,
    const float* __restrict__ bih, const float* __restrict__ bhh,
    const float* __restrict__ Wout, const float* __restrict__ bout,
    float* __restrict__ out)
{
    extern __shared__ float sm[];
    uint32_t sb = (uint32_t)__cvta_generic_to_shared(sm);
    int cta = blockIdx.x;

    if (cta < NGEMM) {
        int j0 = cta * 4;
        const float* Wi1 = Wih + (size_t)3 * Hn * Hn;
        const float* Wh1 = Whh + (size_t)3 * Hn * Hn;
        for (int t = 0; t < Tn; ++t) {
            int p = t & 1;
            gru_phase(sm, sb, g_Xt + (size_t)t * BHn, g_h0[p], g_h0[p ^ 1],
                      Wih, Whh, bih, bhh, j0);
            grid_bar();
            gru_phase(sm, sb, g_h0[p ^ 1], g_h1[p], g_h1[p ^ 1],
                      Wi1, Wh1, bih + 3 * Hn, bhh + 3 * Hn, j0);
            grid_bar();
        }
    } else {
        int r0 = (cta - NGEMM) * 4;
        for (int t = 0; t < Tn; ++t) {
            if (t > 0) proj_step(g_h1[t & 1], Wout, bout, out, r0, t - 1);
            grid_bar();
            grid_bar();
        }
        proj_step(g_h1[((Tn - 1) & 1) ^ 1], Wout, bout, out, r0, Tn - 1);
    }
}

// ---------------- launch ---------------------------------------------------
extern "C" void kernel_launch(void* const* d_in, const int* in_sizes, int n_in,
                              void* d_out, int out_size)
{
    const float* res  = (const float*)d_in[0];
    const float* Wih  = (const float*)d_in[1];
    const float* Whh  = (const float*)d_in[2];
    const float* bih  = (const float*)d_in[3];
    const float* bhh  = (const float*)d_in[4];
    const float* Wout = (const float*)d_in[5];
    const float* bout = (const float*)d_in[6];
    float* out = (float*)d_out;
    (void)in_sizes; (void)n_in; (void)out_size;

    cudaFuncSetAttribute(k_persistent,
                         cudaFuncAttributeMaxDynamicSharedMemorySize, SMB);

    void* h0p = nullptr; void* h1p = nullptr;
    cudaGetSymbolAddress(&h0p, g_h0);
    cudaGetSymbolAddress(&h1p, g_h1);
    cudaMemsetAsync(h0p, 0, sizeof(float) * 2 * BHn, 0);
    cudaMemsetAsync(h1p, 0, sizeof(float) * 2 * BHn, 0);

    dim3 tb(32, 8), tg((Tn + 31) / 32, Hn);
    k_transpose<<<tg, tb>>>(res);

    k_persistent<<<NCTA, 128, SMB>>>(Wih, Whh, bih, bhh, Wout, bout, out);
}